// round 9
// baseline (speedup 1.0000x reference)
#include <cuda_runtime.h>
#include <cuda_bf16.h>
#include <cstdint>

// ---------------------------------------------------------------------------
// STDP delta_w on GB300 — base-sm_103-legal tensor core path (mma.sync bf16).
//
//   trace_t = 0.5*trace_{t-1} + in_t
//   dw[o,i] = sum_{t,b} trace[t,b,i] * out[t,b,o]
//
// R7: warm-up eliminated via linearity. Per chunk c (zero-init trace):
//   dw = sum_c dw_intra(c) + sum_{c>=1} TE(c-1)^T * G(c)
//   G(c)[b,o] = sum_s 0.5^{s+1} out(t0c+s)[b,o],  TE = end-of-chunk trace.
// Main kernel stores TE and G to device scratch; a small correction kernel
// (36 CTAs, K=128 GEMMs) adds the cross-chunk term. Exact to 0.5^55.
// ---------------------------------------------------------------------------

#define T_STEPS 2048
#define B_DIM   128
#define N_IN    256
#define N_OUT   128
#define GT      37                  // time chunks (len 55 or 56)
#define KB      32
#define NBS     (B_DIM / KB)        // 4
#define NTHR    512

// Dynamic smem layout, main kernel (bytes):
//   [0, 131072)        fp32 `in` staging ring: 4 slots x 32KB
//   [131072, 163840)   trace bf16 tile: 2 bufs x 16KB (32 rows x 512B, swizzled)
//   [163840, 180224)   out   bf16 tile: 2 bufs x  8KB (32 rows x 256B, swizzled)
#define SI_STEP  32768
#define TR_OFF   131072
#define TR_BSZ   16384
#define OT_OFF   163840
#define OT_BSZ   8192
#define SM_TOTAL 180224

// Correction kernel smem: TE tile 128x512B = 64KB, G tile 128x256B = 32KB
#define C_TE_OFF 0
#define C_G_OFF  65536
#define C_SM_TOT 98304

#define IN_SLAB  (B_DIM * N_IN  * 4)   // bytes per timestep of gin
#define OUT_SLAB (B_DIM * N_OUT / 4)   // float4 per timestep of gout

// cross-chunk scratch
__device__ float g_TE[GT * B_DIM * N_IN];    // [chunk][b][i]
__device__ float g_G [GT * B_DIM * N_OUT];   // [chunk][b][o]

__device__ __forceinline__ uint32_t smem_u32(const void* p) {
    uint32_t a;
    asm("{ .reg .u64 t; cvta.to.shared.u64 t, %1; cvt.u32.u64 %0, t; }" : "=r"(a) : "l"(p));
    return a;
}

__device__ __forceinline__ void cp16(uint32_t s, const void* g) {
    asm volatile("cp.async.cg.shared.global [%0], [%1], 16;" :: "r"(s), "l"(g) : "memory");
}
#define CP_COMMIT() asm volatile("cp.async.commit_group;" ::: "memory")
#define CP_WAIT3()  asm volatile("cp.async.wait_group 3;" ::: "memory")

__device__ __forceinline__ void ldsm4t(uint32_t* d, uint32_t a) {
    asm volatile("ldmatrix.sync.aligned.m8n8.x4.trans.shared.b16 {%0,%1,%2,%3}, [%4];"
                 : "=r"(d[0]), "=r"(d[1]), "=r"(d[2]), "=r"(d[3]) : "r"(a));
}

__device__ __forceinline__ void mma16816(float* d, const uint32_t* a, const uint32_t* b) {
    asm volatile(
        "mma.sync.aligned.m16n8k16.row.col.f32.bf16.bf16.f32 "
        "{%0,%1,%2,%3},{%4,%5,%6,%7},{%8,%9},{%0,%1,%2,%3};"
        : "+f"(d[0]), "+f"(d[1]), "+f"(d[2]), "+f"(d[3])
        : "r"(a[0]), "r"(a[1]), "r"(a[2]), "r"(a[3]), "r"(b[0]), "r"(b[1]));
}

__device__ __forceinline__ uint32_t pack_bf16x2(float x, float y) {
    __nv_bfloat162 h = __float22bfloat162_rn(make_float2(x, y));
    return *reinterpret_cast<uint32_t*>(&h);
}

__global__ void stdp_zero_kernel(float* __restrict__ p, int n) {
    int i = blockIdx.x * blockDim.x + threadIdx.x;
    if (i < n) p[i] = 0.0f;
}

// ---------------------------------------------------------------------------
__global__ void __launch_bounds__(NTHR, 1)
stdp_main_kernel(const float* __restrict__ gin,   // [T, B, N_IN]
                 const float* __restrict__ gout,  // [T, B, N_OUT]
                 float* __restrict__ dw)          // [N_OUT, N_IN]
{
    extern __shared__ __align__(1024) char smem[];
    const uint32_t sb = smem_u32(smem);
    const int tid = threadIdx.x;
    const int w   = tid >> 5;
    const int l   = tid & 31;

    const int cx  = blockIdx.x;
    const int t0  = (cx * T_STEPS) / GT;
    const int t1  = ((cx + 1) * T_STEPS) / GT;
    const int len = t1 - t0;                 // 55 or 56
    const int b0  = blockIdx.y * KB;

    // ---- per-thread offsets -------------------------------------------------
    int gi_off[4]; uint32_t si_slot[4]; uint32_t sts_in[4];
    int bl_in[4], i4_in[4];
#pragma unroll
    for (int q = 0; q < 4; q++) {
        int f  = tid + 512 * q;
        int bl = f >> 6;
        int i4 = (f & 63) << 2;
        bl_in[q] = bl; i4_in[q] = i4;
        gi_off[q]  = ((b0 + bl) * (N_IN / 4) + (f & 63)) * 16;
        si_slot[q] = (uint32_t)(f * 16);
        sts_in[q]  = (uint32_t)(bl * 512 + (((i4 >> 3) ^ (bl & 7)) << 4) + ((i4 & 7) << 1));
    }
    int go_off[2]; uint32_t sts_out[2];
    int bl_out[2], o4_out[2];
#pragma unroll
    for (int q = 0; q < 2; q++) {
        int f  = tid + 512 * q;
        int bl = f >> 5;
        int o4 = (f & 31) << 2;
        bl_out[q] = bl; o4_out[q] = o4;
        go_off[q]  = (b0 + bl) * (N_OUT / 4) + (f & 31);
        sts_out[q] = (uint32_t)(bl * 256 + (((o4 >> 3) ^ (bl & 7)) << 4) + ((o4 & 7) << 1));
    }

    // ---- ldmatrix source addresses (relative to tile buf base) --------------
    const int wr = w >> 2, wc = w & 3;
    const int obase = wr * 32, ibase = wc * 64;

    uint32_t a_addr[2];
#pragma unroll
    for (int mt = 0; mt < 2; mt++) {
        int b  = (l & 7) + ((l >> 4) << 3);
        int ch = ((obase + mt * 16) >> 3) + ((l >> 3) & 1);
        a_addr[mt] = (uint32_t)(b * 256 + ((ch ^ (b & 7)) << 4));
    }
    uint32_t b_addr[4];
#pragma unroll
    for (int np = 0; np < 4; np++) {
        int b  = (l & 7) + (((l >> 3) & 1) << 3);
        int ch = ((ibase + np * 16) >> 3) + ((l >> 4) & 1);
        b_addr[np] = (uint32_t)(b * 512 + ((ch ^ (b & 7)) << 4));
    }

    // ---- prologue staging: steps t0..t0+3, one group per step ---------------
#pragma unroll
    for (int p = 0; p < 4; p++) {
        const char* src = (const char*)gin + (size_t)(t0 + p) * IN_SLAB;
#pragma unroll
        for (int q = 0; q < 4; q++)
            cp16(sb + p * SI_STEP + si_slot[q], src + gi_off[q]);
        CP_COMMIT();
    }

    // ---- state: zero-init trace (exact per the chunk decomposition) ---------
    float4 tr4[4];
#pragma unroll
    for (int q = 0; q < 4; q++) tr4[q] = make_float4(0.f, 0.f, 0.f, 0.f);

    float4 g4[2];   // G accumulator: sum_s 0.5^{s+1} out(s)
#pragma unroll
    for (int q = 0; q < 2; q++) g4[q] = make_float4(0.f, 0.f, 0.f, 0.f);
    float wgt = 0.5f;

    float acc[2][8][4];
#pragma unroll
    for (int mt = 0; mt < 2; mt++)
#pragma unroll
        for (int nt = 0; nt < 8; nt++)
#pragma unroll
            for (int r = 0; r < 4; r++) acc[mt][nt][r] = 0.0f;

    // out values for the step about to be produced
    float4 voA[2];
    {
        const float4* po = reinterpret_cast<const float4*>(gout) + (size_t)t0 * OUT_SLAB;
#pragma unroll
        for (int q = 0; q < 2; q++) voA[q] = po[go_off[q]];
    }

    // produce(sp): build bf16 tiles for step sp, accumulate G, refill staging
    // with sp+4, prefetch out(sp+1). Assumes voA holds out(sp) on entry.
    auto produce = [&](int sp) {
        const int slot = sp & 3;
        const int buf  = sp & 1;
        CP_WAIT3();   // staging slot for step sp complete
        const char* sg = smem + slot * SI_STEP;
        char* td = smem + TR_OFF + buf * TR_BSZ;
#pragma unroll
        for (int q = 0; q < 4; q++) {
            float4 v = *reinterpret_cast<const float4*>(sg + si_slot[q]);
            tr4[q].x = fmaf(0.5f, tr4[q].x, v.x);
            tr4[q].y = fmaf(0.5f, tr4[q].y, v.y);
            tr4[q].z = fmaf(0.5f, tr4[q].z, v.z);
            tr4[q].w = fmaf(0.5f, tr4[q].w, v.w);
            uint2 u = make_uint2(pack_bf16x2(tr4[q].x, tr4[q].y),
                                 pack_bf16x2(tr4[q].z, tr4[q].w));
            *reinterpret_cast<uint2*>(td + sts_in[q]) = u;
        }
        char* od = smem + OT_OFF + buf * OT_BSZ;
#pragma unroll
        for (int q = 0; q < 2; q++) {
            uint2 u = make_uint2(pack_bf16x2(voA[q].x, voA[q].y),
                                 pack_bf16x2(voA[q].z, voA[q].w));
            *reinterpret_cast<uint2*>(od + sts_out[q]) = u;
            g4[q].x = fmaf(wgt, voA[q].x, g4[q].x);
            g4[q].y = fmaf(wgt, voA[q].y, g4[q].y);
            g4[q].z = fmaf(wgt, voA[q].z, g4[q].z);
            g4[q].w = fmaf(wgt, voA[q].w, g4[q].w);
        }
        wgt *= 0.5f;
        // prefetch out(sp+1)
        if (sp + 1 < len) {
            const float4* po = reinterpret_cast<const float4*>(gout)
                             + (size_t)(t0 + sp + 1) * OUT_SLAB;
#pragma unroll
            for (int q = 0; q < 2; q++) voA[q] = po[go_off[q]];
        }
        // refill this slot with step sp+4
        if (sp + 4 < len) {
            const char* src = (const char*)gin + (size_t)(t0 + sp + 4) * IN_SLAB;
#pragma unroll
            for (int q = 0; q < 4; q++) cp16(sb + slot * SI_STEP + si_slot[q], src + gi_off[q]);
        }
        CP_COMMIT();
    };

    auto do_mma = [&](int buf) {
        const uint32_t abase = sb + OT_OFF + buf * OT_BSZ;
        const uint32_t bbase = sb + TR_OFF + buf * TR_BSZ;
#pragma unroll
        for (int kb = 0; kb < 2; kb++) {
            uint32_t af[2][4];
            ldsm4t(af[0], abase + a_addr[0] + kb * 16 * 256);
            ldsm4t(af[1], abase + a_addr[1] + kb * 16 * 256);
#pragma unroll
            for (int np = 0; np < 4; np++) {
                uint32_t bf[4];
                ldsm4t(bf, bbase + b_addr[np] + kb * 16 * 512);
#pragma unroll
                for (int mt = 0; mt < 2; mt++) {
                    mma16816(acc[mt][2 * np],     af[mt], bf);
                    mma16816(acc[mt][2 * np + 1], af[mt], bf + 2);
                }
            }
        }
    };

    produce(0);
    __syncthreads();

    for (int s = 0; s < len; s++) {
        if ((w & 1) == 0) {
            do_mma(s & 1);
            if (s + 1 < len) produce(s + 1);
        } else {
            if (s + 1 < len) produce(s + 1);
            do_mma(s & 1);
        }
        __syncthreads();
    }

    // ---- store TE (end-of-chunk trace) and G to scratch ---------------------
    {
        float* te = g_TE + (size_t)cx * (B_DIM * N_IN);
#pragma unroll
        for (int q = 0; q < 4; q++)
            *reinterpret_cast<float4*>(te + (b0 + bl_in[q]) * N_IN + i4_in[q]) = tr4[q];
        float* gg = g_G + (size_t)cx * (B_DIM * N_OUT);
#pragma unroll
        for (int q = 0; q < 2; q++)
            *reinterpret_cast<float4*>(gg + (b0 + bl_out[q]) * N_OUT + o4_out[q]) = g4[q];
    }

    // ---- epilogue: vector reductions into dw --------------------------------
#pragma unroll
    for (int mt = 0; mt < 2; mt++) {
#pragma unroll
        for (int nt = 0; nt < 8; nt++) {
            const int o = obase + mt * 16 + (l >> 2);
            const int i = ibase + nt * 8 + ((l & 3) << 1);
            float* p = dw + (size_t)o * N_IN + i;
            asm volatile("red.global.add.v2.f32 [%0], {%1,%2};"
                         :: "l"(p), "f"(acc[mt][nt][0]), "f"(acc[mt][nt][1]) : "memory");
            asm volatile("red.global.add.v2.f32 [%0], {%1,%2};"
                         :: "l"(p + 8 * N_IN), "f"(acc[mt][nt][2]), "f"(acc[mt][nt][3]) : "memory");
        }
    }
}

// ---------------------------------------------------------------------------
// Cross-chunk correction: dw += TE(c-1)^T * G(c), K = 128 (batch), c = 1..GT-1.
__global__ void __launch_bounds__(NTHR, 1)
stdp_corr_kernel(float* __restrict__ dw)
{
    extern __shared__ __align__(1024) char smem[];
    const uint32_t sb = smem_u32(smem);
    const int tid = threadIdx.x;
    const int w   = tid >> 5;
    const int l   = tid & 31;
    const int c   = blockIdx.x + 1;

    // ---- load TE(c-1) -> bf16 swizzled B-tile (128 rows x 512B) -------------
    {
        const float* te = g_TE + (size_t)(c - 1) * (B_DIM * N_IN);
#pragma unroll
        for (int q = 0; q < 16; q++) {
            int f  = tid + 512 * q;
            int b  = f >> 6;
            int i4 = (f & 63) << 2;
            float4 v = *reinterpret_cast<const float4*>(te + b * N_IN + i4);
            uint2 u = make_uint2(pack_bf16x2(v.x, v.y), pack_bf16x2(v.z, v.w));
            uint32_t off = (uint32_t)(b * 512 + (((i4 >> 3) ^ (b & 7)) << 4) + ((i4 & 7) << 1));
            *reinterpret_cast<uint2*>(smem + C_TE_OFF + off) = u;
        }
        const float* gg = g_G + (size_t)c * (B_DIM * N_OUT);
#pragma unroll
        for (int q = 0; q < 8; q++) {
            int f  = tid + 512 * q;
            int b  = f >> 5;
            int o4 = (f & 31) << 2;
            float4 v = *reinterpret_cast<const float4*>(gg + b * N_OUT + o4);
            uint2 u = make_uint2(pack_bf16x2(v.x, v.y), pack_bf16x2(v.z, v.w));
            uint32_t off = (uint32_t)(b * 256 + (((o4 >> 3) ^ (b & 7)) << 4) + ((o4 & 7) << 1));
            *reinterpret_cast<uint2*>(smem + C_G_OFF + off) = u;
        }
    }
    __syncthreads();

    // ---- MMA: warp tile 32(o) x 64(i), K = 128 ------------------------------
    const int wr = w >> 2, wc = w & 3;
    const int obase = wr * 32, ibase = wc * 64;

    uint32_t a_addr[2];
#pragma unroll
    for (int mt = 0; mt < 2; mt++) {
        int b  = (l & 7) + ((l >> 4) << 3);
        int ch = ((obase + mt * 16) >> 3) + ((l >> 3) & 1);
        a_addr[mt] = (uint32_t)(b * 256 + ((ch ^ (b & 7)) << 4));
    }
    uint32_t b_addr[4];
#pragma unroll
    for (int np = 0; np < 4; np++) {
        int b  = (l & 7) + (((l >> 3) & 1) << 3);
        int ch = ((ibase + np * 16) >> 3) + ((l >> 4) & 1);
        b_addr[np] = (uint32_t)(b * 512 + ((ch ^ (b & 7)) << 4));
    }

    float acc[2][8][4];
#pragma unroll
    for (int mt = 0; mt < 2; mt++)
#pragma unroll
        for (int nt = 0; nt < 8; nt++)
#pragma unroll
            for (int r = 0; r < 4; r++) acc[mt][nt][r] = 0.0f;

#pragma unroll
    for (int kb = 0; kb < 8; kb++) {
        uint32_t af[2][4];
        ldsm4t(af[0], sb + C_G_OFF + a_addr[0] + kb * 16 * 256);
        ldsm4t(af[1], sb + C_G_OFF + a_addr[1] + kb * 16 * 256);
#pragma unroll
        for (int np = 0; np < 4; np++) {
            uint32_t bf[4];
            ldsm4t(bf, sb + C_TE_OFF + b_addr[np] + kb * 16 * 512);
#pragma unroll
            for (int mt = 0; mt < 2; mt++) {
                mma16816(acc[mt][2 * np],     af[mt], bf);
                mma16816(acc[mt][2 * np + 1], af[mt], bf + 2);
            }
        }
    }

#pragma unroll
    for (int mt = 0; mt < 2; mt++) {
#pragma unroll
        for (int nt = 0; nt < 8; nt++) {
            const int o = obase + mt * 16 + (l >> 2);
            const int i = ibase + nt * 8 + ((l & 3) << 1);
            float* p = dw + (size_t)o * N_IN + i;
            asm volatile("red.global.add.v2.f32 [%0], {%1,%2};"
                         :: "l"(p), "f"(acc[mt][nt][0]), "f"(acc[mt][nt][1]) : "memory");
            asm volatile("red.global.add.v2.f32 [%0], {%1,%2};"
                         :: "l"(p + 8 * N_IN), "f"(acc[mt][nt][2]), "f"(acc[mt][nt][3]) : "memory");
        }
    }
}

extern "C" void kernel_launch(void* const* d_in, const int* in_sizes, int n_in,
                              void* d_out, int out_size) {
    (void)in_sizes; (void)n_in; (void)out_size;
    const float* gin  = (const float*)d_in[0];   // in_spikes  [T, B, N_IN]
    const float* gout = (const float*)d_in[1];   // out_spikes [T, B, N_OUT]
    float* dw = (float*)d_out;                   // [N_OUT, N_IN]

    stdp_zero_kernel<<<(N_OUT * N_IN + NTHR - 1) / NTHR, NTHR>>>(dw, N_OUT * N_IN);

    cudaFuncSetAttribute(stdp_main_kernel,
                         cudaFuncAttributeMaxDynamicSharedMemorySize, SM_TOTAL);
    dim3 grid(GT, NBS);
    stdp_main_kernel<<<grid, NTHR, SM_TOTAL>>>(gin, gout, dw);

    cudaFuncSetAttribute(stdp_corr_kernel,
                         cudaFuncAttributeMaxDynamicSharedMemorySize, C_SM_TOT);
    stdp_corr_kernel<<<GT - 1, NTHR, C_SM_TOT>>>(dw);
}

// round 10
// speedup vs baseline: 1.0201x; 1.0201x over previous
#include <cuda_runtime.h>
#include <cuda_bf16.h>
#include <cstdint>

// ---------------------------------------------------------------------------
// STDP delta_w on GB300 — base-sm_103-legal tensor core path (mma.sync bf16).
//
//   trace_t = 0.5*trace_{t-1} + in_t
//   dw[o,i] = sum_{t,b} trace[t,b,i] * out[t,b,o]
//
// R9: chunk decomposition (no warm-up reads) kept from R7, with affine
// per-q addressing (q-invariant swizzle terms) to stay under the 128-reg
// ceiling without spills:
//   dw = sum_c dw_intra(c) + sum_{c>=1} TE(c-1)^T * G(c)
//   G(c)[b,o] = sum_s 0.5^{s+1} out(t0c+s)[b,o],  TE = end-of-chunk trace.
// ---------------------------------------------------------------------------

#define T_STEPS 2048
#define B_DIM   128
#define N_IN    256
#define N_OUT   128
#define GT      37                  // time chunks (len 55 or 56)
#define KB      32
#define NBS     (B_DIM / KB)        // 4
#define NTHR    512

// Dynamic smem layout, main kernel (bytes):
//   [0, 131072)        fp32 `in` staging ring: 4 slots x 32KB
//   [131072, 163840)   trace bf16 tile: 2 bufs x 16KB (32 rows x 512B, swizzled)
//   [163840, 180224)   out   bf16 tile: 2 bufs x  8KB (32 rows x 256B, swizzled)
#define SI_STEP  32768
#define TR_OFF   131072
#define TR_BSZ   16384
#define OT_OFF   163840
#define OT_BSZ   8192
#define SM_TOTAL 180224

// Correction kernel smem: TE tile 128x512B = 64KB, G tile 128x256B = 32KB
#define C_TE_OFF 0
#define C_G_OFF  65536
#define C_SM_TOT 98304

#define IN_SLAB  (B_DIM * N_IN  * 4)   // bytes per timestep of gin
#define OUT_SLAB (B_DIM * N_OUT / 4)   // float4 per timestep of gout

// cross-chunk scratch
__device__ float g_TE[GT * B_DIM * N_IN];    // [chunk][b][i]
__device__ float g_G [GT * B_DIM * N_OUT];   // [chunk][b][o]

__device__ __forceinline__ uint32_t smem_u32(const void* p) {
    uint32_t a;
    asm("{ .reg .u64 t; cvta.to.shared.u64 t, %1; cvt.u32.u64 %0, t; }" : "=r"(a) : "l"(p));
    return a;
}

__device__ __forceinline__ void cp16(uint32_t s, const void* g) {
    asm volatile("cp.async.cg.shared.global [%0], [%1], 16;" :: "r"(s), "l"(g) : "memory");
}
#define CP_COMMIT() asm volatile("cp.async.commit_group;" ::: "memory")
#define CP_WAIT3()  asm volatile("cp.async.wait_group 3;" ::: "memory")

__device__ __forceinline__ void ldsm4t(uint32_t* d, uint32_t a) {
    asm volatile("ldmatrix.sync.aligned.m8n8.x4.trans.shared.b16 {%0,%1,%2,%3}, [%4];"
                 : "=r"(d[0]), "=r"(d[1]), "=r"(d[2]), "=r"(d[3]) : "r"(a));
}

__device__ __forceinline__ void mma16816(float* d, const uint32_t* a, const uint32_t* b) {
    asm volatile(
        "mma.sync.aligned.m16n8k16.row.col.f32.bf16.bf16.f32 "
        "{%0,%1,%2,%3},{%4,%5,%6,%7},{%8,%9},{%0,%1,%2,%3};"
        : "+f"(d[0]), "+f"(d[1]), "+f"(d[2]), "+f"(d[3])
        : "r"(a[0]), "r"(a[1]), "r"(a[2]), "r"(a[3]), "r"(b[0]), "r"(b[1]));
}

__device__ __forceinline__ uint32_t pack_bf16x2(float x, float y) {
    __nv_bfloat162 h = __float22bfloat162_rn(make_float2(x, y));
    return *reinterpret_cast<uint32_t*>(&h);
}

__global__ void stdp_zero_kernel(float* __restrict__ p, int n) {
    int i = blockIdx.x * blockDim.x + threadIdx.x;
    if (i < n) p[i] = 0.0f;
}

// ---------------------------------------------------------------------------
__global__ void __launch_bounds__(NTHR, 1)
stdp_main_kernel(const float* __restrict__ gin,   // [T, B, N_IN]
                 const float* __restrict__ gout,  // [T, B, N_OUT]
                 float* __restrict__ dw)          // [N_OUT, N_IN]
{
    extern __shared__ __align__(1024) char smem[];
    const uint32_t sb = smem_u32(smem);
    const int tid = threadIdx.x;
    const int w   = tid >> 5;
    const int l   = tid & 31;

    const int cx  = blockIdx.x;
    const int t0  = (cx * T_STEPS) / GT;
    const int t1  = ((cx + 1) * T_STEPS) / GT;
    const int len = t1 - t0;                 // 55 or 56
    const int b0  = blockIdx.y * KB;

    // ---- affine per-thread base offsets (q-strides are compile-time) -------
    // in (q<4, f = tid+512q): bl = (tid>>6)+8q, i4 = (tid&63)<<2 (q-invariant)
    //   gi  : +8192 B/q   si: +8192 B/q   sts_in: +4096 B/q
    // out (q<2): bl = (tid>>5)+16q, o4 = (tid&31)<<2 (q-invariant)
    //   go  : +512 float4/q   sts_out: +4096 B/q
    const int bi  = tid >> 6;               // in-base batch row (0..7)
    const int i4  = (tid & 63) << 2;
    const int gi0 = ((b0 + bi) * (N_IN / 4) + (tid & 63)) * 16;      // bytes
    const uint32_t si0 = (uint32_t)(tid * 16);                        // bytes
    const uint32_t stsin0 = (uint32_t)(bi * 512 + (((i4 >> 3) ^ (bi & 7)) << 4)
                                       + ((i4 & 7) << 1));
    const int bo  = tid >> 5;               // out-base batch row (0..15)
    const int o4  = (tid & 31) << 2;
    const int go0 = (b0 + bo) * (N_OUT / 4) + (tid & 31);             // float4
    const uint32_t stsout0 = (uint32_t)(bo * 256 + (((o4 >> 3) ^ (bo & 7)) << 4)
                                        + ((o4 & 7) << 1));

    // ---- ldmatrix source addresses (relative to tile buf base) --------------
    const int wr = w >> 2, wc = w & 3;
    const int obase = wr * 32, ibase = wc * 64;

    uint32_t a_addr[2];
#pragma unroll
    for (int mt = 0; mt < 2; mt++) {
        int b  = (l & 7) + ((l >> 4) << 3);
        int ch = ((obase + mt * 16) >> 3) + ((l >> 3) & 1);
        a_addr[mt] = (uint32_t)(b * 256 + ((ch ^ (b & 7)) << 4));
    }
    uint32_t b_addr[4];
#pragma unroll
    for (int np = 0; np < 4; np++) {
        int b  = (l & 7) + (((l >> 3) & 1) << 3);
        int ch = ((ibase + np * 16) >> 3) + ((l >> 4) & 1);
        b_addr[np] = (uint32_t)(b * 512 + ((ch ^ (b & 7)) << 4));
    }

    // ---- prologue staging: steps t0..t0+3, one group per step ---------------
#pragma unroll
    for (int p = 0; p < 4; p++) {
        const char* src = (const char*)gin + (size_t)(t0 + p) * IN_SLAB + gi0;
#pragma unroll
        for (int q = 0; q < 4; q++)
            cp16(sb + p * SI_STEP + si0 + q * 8192, src + q * 8192);
        CP_COMMIT();
    }

    // ---- state: zero-init trace (exact per the chunk decomposition) ---------
    float4 tr4[4];
#pragma unroll
    for (int q = 0; q < 4; q++) tr4[q] = make_float4(0.f, 0.f, 0.f, 0.f);

    float4 g4[2];   // G accumulator: sum_s 0.5^{s+1} out(s)
#pragma unroll
    for (int q = 0; q < 2; q++) g4[q] = make_float4(0.f, 0.f, 0.f, 0.f);
    float wgt = 0.5f;

    float acc[2][8][4];
#pragma unroll
    for (int mt = 0; mt < 2; mt++)
#pragma unroll
        for (int nt = 0; nt < 8; nt++)
#pragma unroll
            for (int r = 0; r < 4; r++) acc[mt][nt][r] = 0.0f;

    // out values for the step about to be produced
    float4 voA[2];
    {
        const float4* po = reinterpret_cast<const float4*>(gout)
                         + (size_t)t0 * OUT_SLAB + go0;
#pragma unroll
        for (int q = 0; q < 2; q++) voA[q] = po[q * 512];
    }

    // produce(sp): build bf16 tiles for step sp, accumulate G, refill staging
    // with sp+4, prefetch out(sp+1). Assumes voA holds out(sp) on entry.
    auto produce = [&](int sp) {
        const int slot = sp & 3;
        const int buf  = sp & 1;
        CP_WAIT3();   // staging slot for step sp complete
        const char* sg = smem + slot * SI_STEP + si0;
        char* td = smem + TR_OFF + buf * TR_BSZ + stsin0;
#pragma unroll
        for (int q = 0; q < 4; q++) {
            float4 v = *reinterpret_cast<const float4*>(sg + q * 8192);
            tr4[q].x = fmaf(0.5f, tr4[q].x, v.x);
            tr4[q].y = fmaf(0.5f, tr4[q].y, v.y);
            tr4[q].z = fmaf(0.5f, tr4[q].z, v.z);
            tr4[q].w = fmaf(0.5f, tr4[q].w, v.w);
            uint2 u = make_uint2(pack_bf16x2(tr4[q].x, tr4[q].y),
                                 pack_bf16x2(tr4[q].z, tr4[q].w));
            *reinterpret_cast<uint2*>(td + q * 4096) = u;
        }
        char* od = smem + OT_OFF + buf * OT_BSZ + stsout0;
#pragma unroll
        for (int q = 0; q < 2; q++) {
            uint2 u = make_uint2(pack_bf16x2(voA[q].x, voA[q].y),
                                 pack_bf16x2(voA[q].z, voA[q].w));
            *reinterpret_cast<uint2*>(od + q * 4096) = u;
            g4[q].x = fmaf(wgt, voA[q].x, g4[q].x);
            g4[q].y = fmaf(wgt, voA[q].y, g4[q].y);
            g4[q].z = fmaf(wgt, voA[q].z, g4[q].z);
            g4[q].w = fmaf(wgt, voA[q].w, g4[q].w);
        }
        wgt *= 0.5f;
        // prefetch out(sp+1)
        if (sp + 1 < len) {
            const float4* po = reinterpret_cast<const float4*>(gout)
                             + (size_t)(t0 + sp + 1) * OUT_SLAB + go0;
#pragma unroll
            for (int q = 0; q < 2; q++) voA[q] = po[q * 512];
        }
        // refill this slot with step sp+4
        if (sp + 4 < len) {
            const char* src = (const char*)gin + (size_t)(t0 + sp + 4) * IN_SLAB + gi0;
#pragma unroll
            for (int q = 0; q < 4; q++)
                cp16(sb + slot * SI_STEP + si0 + q * 8192, src + q * 8192);
        }
        CP_COMMIT();
    };

    auto do_mma = [&](int buf) {
        const uint32_t abase = sb + OT_OFF + buf * OT_BSZ;
        const uint32_t bbase = sb + TR_OFF + buf * TR_BSZ;
#pragma unroll
        for (int kb = 0; kb < 2; kb++) {
            uint32_t af[2][4];
            ldsm4t(af[0], abase + a_addr[0] + kb * 16 * 256);
            ldsm4t(af[1], abase + a_addr[1] + kb * 16 * 256);
#pragma unroll
            for (int np = 0; np < 4; np++) {
                uint32_t bf[4];
                ldsm4t(bf, bbase + b_addr[np] + kb * 16 * 512);
#pragma unroll
                for (int mt = 0; mt < 2; mt++) {
                    mma16816(acc[mt][2 * np],     af[mt], bf);
                    mma16816(acc[mt][2 * np + 1], af[mt], bf + 2);
                }
            }
        }
    };

    produce(0);
    __syncthreads();

    for (int s = 0; s < len; s++) {
        if ((w & 1) == 0) {
            do_mma(s & 1);
            if (s + 1 < len) produce(s + 1);
        } else {
            if (s + 1 < len) produce(s + 1);
            do_mma(s & 1);
        }
        __syncthreads();
    }

    // ---- store TE (end-of-chunk trace) and G to scratch (affine in q) -------
    {
        float* te = g_TE + (size_t)cx * (B_DIM * N_IN) + (b0 + bi) * N_IN + i4;
#pragma unroll
        for (int q = 0; q < 4; q++)
            *reinterpret_cast<float4*>(te + q * (8 * N_IN)) = tr4[q];
        float* gg = g_G + (size_t)cx * (B_DIM * N_OUT) + (b0 + bo) * N_OUT + o4;
#pragma unroll
        for (int q = 0; q < 2; q++)
            *reinterpret_cast<float4*>(gg + q * (16 * N_OUT)) = g4[q];
    }

    // ---- epilogue: vector reductions into dw --------------------------------
#pragma unroll
    for (int mt = 0; mt < 2; mt++) {
#pragma unroll
        for (int nt = 0; nt < 8; nt++) {
            const int o = obase + mt * 16 + (l >> 2);
            const int i = ibase + nt * 8 + ((l & 3) << 1);
            float* p = dw + (size_t)o * N_IN + i;
            asm volatile("red.global.add.v2.f32 [%0], {%1,%2};"
                         :: "l"(p), "f"(acc[mt][nt][0]), "f"(acc[mt][nt][1]) : "memory");
            asm volatile("red.global.add.v2.f32 [%0], {%1,%2};"
                         :: "l"(p + 8 * N_IN), "f"(acc[mt][nt][2]), "f"(acc[mt][nt][3]) : "memory");
        }
    }
}

// ---------------------------------------------------------------------------
// Cross-chunk correction: dw += TE(c-1)^T * G(c), K = 128 (batch), c = 1..GT-1.
__global__ void __launch_bounds__(NTHR, 1)
stdp_corr_kernel(float* __restrict__ dw)
{
    extern __shared__ __align__(1024) char smem[];
    const uint32_t sb = smem_u32(smem);
    const int tid = threadIdx.x;
    const int w   = tid >> 5;
    const int l   = tid & 31;
    const int c   = blockIdx.x + 1;

    // ---- load TE(c-1) / G(c) -> bf16 swizzled tiles -------------------------
    {
        const float* te = g_TE + (size_t)(c - 1) * (B_DIM * N_IN);
#pragma unroll
        for (int q = 0; q < 16; q++) {
            int f  = tid + 512 * q;
            int b  = f >> 6;
            int i4 = (f & 63) << 2;
            float4 v = *reinterpret_cast<const float4*>(te + b * N_IN + i4);
            uint2 u = make_uint2(pack_bf16x2(v.x, v.y), pack_bf16x2(v.z, v.w));
            uint32_t off = (uint32_t)(b * 512 + (((i4 >> 3) ^ (b & 7)) << 4) + ((i4 & 7) << 1));
            *reinterpret_cast<uint2*>(smem + C_TE_OFF + off) = u;
        }
        const float* gg = g_G + (size_t)c * (B_DIM * N_OUT);
#pragma unroll
        for (int q = 0; q < 8; q++) {
            int f  = tid + 512 * q;
            int b  = f >> 5;
            int o4 = (f & 31) << 2;
            float4 v = *reinterpret_cast<const float4*>(gg + b * N_OUT + o4);
            uint2 u = make_uint2(pack_bf16x2(v.x, v.y), pack_bf16x2(v.z, v.w));
            uint32_t off = (uint32_t)(b * 256 + (((o4 >> 3) ^ (b & 7)) << 4) + ((o4 & 7) << 1));
            *reinterpret_cast<uint2*>(smem + C_G_OFF + off) = u;
        }
    }
    __syncthreads();

    // ---- MMA: warp tile 32(o) x 64(i), K = 128 ------------------------------
    const int wr = w >> 2, wc = w & 3;
    const int obase = wr * 32, ibase = wc * 64;

    uint32_t a_addr[2];
#pragma unroll
    for (int mt = 0; mt < 2; mt++) {
        int b  = (l & 7) + ((l >> 4) << 3);
        int ch = ((obase + mt * 16) >> 3) + ((l >> 3) & 1);
        a_addr[mt] = (uint32_t)(b * 256 + ((ch ^ (b & 7)) << 4));
    }
    uint32_t b_addr[4];
#pragma unroll
    for (int np = 0; np < 4; np++) {
        int b  = (l & 7) + (((l >> 3) & 1) << 3);
        int ch = ((ibase + np * 16) >> 3) + ((l >> 4) & 1);
        b_addr[np] = (uint32_t)(b * 512 + ((ch ^ (b & 7)) << 4));
    }

    float acc[2][8][4];
#pragma unroll
    for (int mt = 0; mt < 2; mt++)
#pragma unroll
        for (int nt = 0; nt < 8; nt++)
#pragma unroll
            for (int r = 0; r < 4; r++) acc[mt][nt][r] = 0.0f;

#pragma unroll
    for (int kb = 0; kb < 8; kb++) {
        uint32_t af[2][4];
        ldsm4t(af[0], sb + C_G_OFF + a_addr[0] + kb * 16 * 256);
        ldsm4t(af[1], sb + C_G_OFF + a_addr[1] + kb * 16 * 256);
#pragma unroll
        for (int np = 0; np < 4; np++) {
            uint32_t bf[4];
            ldsm4t(bf, sb + C_TE_OFF + b_addr[np] + kb * 16 * 512);
#pragma unroll
            for (int mt = 0; mt < 2; mt++) {
                mma16816(acc[mt][2 * np],     af[mt], bf);
                mma16816(acc[mt][2 * np + 1], af[mt], bf + 2);
            }
        }
    }

#pragma unroll
    for (int mt = 0; mt < 2; mt++) {
#pragma unroll
        for (int nt = 0; nt < 8; nt++) {
            const int o = obase + mt * 16 + (l >> 2);
            const int i = ibase + nt * 8 + ((l & 3) << 1);
            float* p = dw + (size_t)o * N_IN + i;
            asm volatile("red.global.add.v2.f32 [%0], {%1,%2};"
                         :: "l"(p), "f"(acc[mt][nt][0]), "f"(acc[mt][nt][1]) : "memory");
            asm volatile("red.global.add.v2.f32 [%0], {%1,%2};"
                         :: "l"(p + 8 * N_IN), "f"(acc[mt][nt][2]), "f"(acc[mt][nt][3]) : "memory");
        }
    }
}

extern "C" void kernel_launch(void* const* d_in, const int* in_sizes, int n_in,
                              void* d_out, int out_size) {
    (void)in_sizes; (void)n_in; (void)out_size;
    const float* gin  = (const float*)d_in[0];   // in_spikes  [T, B, N_IN]
    const float* gout = (const float*)d_in[1];   // out_spikes [T, B, N_OUT]
    float* dw = (float*)d_out;                   // [N_OUT, N_IN]

    stdp_zero_kernel<<<(N_OUT * N_IN + NTHR - 1) / NTHR, NTHR>>>(dw, N_OUT * N_IN);

    cudaFuncSetAttribute(stdp_main_kernel,
                         cudaFuncAttributeMaxDynamicSharedMemorySize, SM_TOTAL);
    dim3 grid(GT, NBS);
    stdp_main_kernel<<<grid, NTHR, SM_TOTAL>>>(gin, gout, dw);

    cudaFuncSetAttribute(stdp_corr_kernel,
                         cudaFuncAttributeMaxDynamicSharedMemorySize, C_SM_TOT);
    stdp_corr_kernel<<<GT - 1, NTHR, C_SM_TOT>>>(dw);
}

// round 11
// speedup vs baseline: 1.1283x; 1.1061x over previous
#include <cuda_runtime.h>
#include <cuda_bf16.h>
#include <cstdint>

// ---------------------------------------------------------------------------
// STDP delta_w on GB300 — base-sm_103-legal tensor core path (mma.sync bf16).
//
//   trace_t = 0.5*trace_{t-1} + in_t
//   dw[o,i] = sum_{t,b} trace[t,b,i] * out[t,b,o]
//
// R10: chunk decomposition (no warm-up reads) with the trace recursion run
// natively in bf16x2 registers (8 regs instead of 16) and G accumulated in
// bf16x2 (5 regs instead of 9) — the whole mainloop state now fits under the
// 128-reg ceiling without spills. TE/G scratch stored as bf16x2.
//   dw = sum_c dw_intra(c) + sum_{c>=1} TE(c-1)^T * G(c)
//   G(c)[b,o] = sum_s 0.5^{s+1} out(t0c+s)[b,o],  TE = end-of-chunk trace.
// ---------------------------------------------------------------------------

#define T_STEPS 2048
#define B_DIM   128
#define N_IN    256
#define N_OUT   128
#define GT      37                  // time chunks (len 55 or 56)
#define KB      32
#define NBS     (B_DIM / KB)        // 4
#define NTHR    512

// Dynamic smem layout, main kernel (bytes):
//   [0, 131072)        fp32 `in` staging ring: 4 slots x 32KB
//   [131072, 163840)   trace bf16 tile: 2 bufs x 16KB (32 rows x 512B, swizzled)
//   [163840, 180224)   out   bf16 tile: 2 bufs x  8KB (32 rows x 256B, swizzled)
#define SI_STEP  32768
#define TR_OFF   131072
#define TR_BSZ   16384
#define OT_OFF   163840
#define OT_BSZ   8192
#define SM_TOTAL 180224

// Correction kernel smem: TE tile 128x512B = 64KB, G tile 128x256B = 32KB
#define C_TE_OFF 0
#define C_G_OFF  65536
#define C_SM_TOT 98304

#define IN_SLAB  (B_DIM * N_IN  * 4)   // bytes per timestep of gin
#define OUT_SLAB (B_DIM * N_OUT / 4)   // float4 per timestep of gout

#define BF_HALF2 0x3F003F00u           // bf16x2 (0.5, 0.5)

// cross-chunk scratch, bf16x2 packed
__device__ uint32_t g_TE_u[GT * B_DIM * (N_IN / 2)];    // [chunk][b][i/2]
__device__ uint32_t g_G_u [GT * B_DIM * (N_OUT / 2)];   // [chunk][b][o/2]

__device__ __forceinline__ uint32_t smem_u32(const void* p) {
    uint32_t a;
    asm("{ .reg .u64 t; cvta.to.shared.u64 t, %1; cvt.u32.u64 %0, t; }" : "=r"(a) : "l"(p));
    return a;
}

__device__ __forceinline__ void cp16(uint32_t s, const void* g) {
    asm volatile("cp.async.cg.shared.global [%0], [%1], 16;" :: "r"(s), "l"(g) : "memory");
}
#define CP_COMMIT() asm volatile("cp.async.commit_group;" ::: "memory")
#define CP_WAIT3()  asm volatile("cp.async.wait_group 3;" ::: "memory")

__device__ __forceinline__ void ldsm4t(uint32_t* d, uint32_t a) {
    asm volatile("ldmatrix.sync.aligned.m8n8.x4.trans.shared.b16 {%0,%1,%2,%3}, [%4];"
                 : "=r"(d[0]), "=r"(d[1]), "=r"(d[2]), "=r"(d[3]) : "r"(a));
}

__device__ __forceinline__ void mma16816(float* d, const uint32_t* a, const uint32_t* b) {
    asm volatile(
        "mma.sync.aligned.m16n8k16.row.col.f32.bf16.bf16.f32 "
        "{%0,%1,%2,%3},{%4,%5,%6,%7},{%8,%9},{%0,%1,%2,%3};"
        : "+f"(d[0]), "+f"(d[1]), "+f"(d[2]), "+f"(d[3])
        : "r"(a[0]), "r"(a[1]), "r"(a[2]), "r"(a[3]), "r"(b[0]), "r"(b[1]));
}

// d = a*b + c in packed bf16x2 (single rounding per lane)
__device__ __forceinline__ uint32_t hfma2(uint32_t a, uint32_t b, uint32_t c) {
    uint32_t d;
    asm("fma.rn.bf16x2 %0, %1, %2, %3;" : "=r"(d) : "r"(a), "r"(b), "r"(c));
    return d;
}

// pack (lo, hi) floats -> bf16x2
__device__ __forceinline__ uint32_t cvt2bf(float hi, float lo) {
    uint32_t r;
    asm("cvt.rn.bf16x2.f32 %0, %1, %2;" : "=r"(r) : "f"(hi), "f"(lo));
    return r;
}

__global__ void stdp_zero_kernel(float4* __restrict__ p) {
    p[blockIdx.x * blockDim.x + threadIdx.x] = make_float4(0.f, 0.f, 0.f, 0.f);
}

// ---------------------------------------------------------------------------
__global__ void __launch_bounds__(NTHR, 1)
stdp_main_kernel(const float* __restrict__ gin,   // [T, B, N_IN]
                 const float* __restrict__ gout,  // [T, B, N_OUT]
                 float* __restrict__ dw)          // [N_OUT, N_IN]
{
    extern __shared__ __align__(1024) char smem[];
    const uint32_t sb = smem_u32(smem);
    const int tid = threadIdx.x;
    const int w   = tid >> 5;
    const int l   = tid & 31;

    const int cx  = blockIdx.x;
    const int t0  = (cx * T_STEPS) / GT;
    const int t1  = ((cx + 1) * T_STEPS) / GT;
    const int len = t1 - t0;                 // 55 or 56
    const int b0  = blockIdx.y * KB;

    // ---- affine per-thread base offsets (q-strides compile-time) ------------
    const int bi  = tid >> 6;               // in-base batch row (0..7)
    const int i4  = (tid & 63) << 2;
    const int gi0 = ((b0 + bi) * (N_IN / 4) + (tid & 63)) * 16;      // bytes
    const uint32_t si0 = (uint32_t)(tid * 16);                        // bytes
    const uint32_t stsin0 = (uint32_t)(bi * 512 + (((i4 >> 3) ^ (bi & 7)) << 4)
                                       + ((i4 & 7) << 1));
    const int bo  = tid >> 5;               // out-base batch row (0..15)
    const int o4  = (tid & 31) << 2;
    const int go0 = (b0 + bo) * (N_OUT / 4) + (tid & 31);             // float4
    const uint32_t stsout0 = (uint32_t)(bo * 256 + (((o4 >> 3) ^ (bo & 7)) << 4)
                                        + ((o4 & 7) << 1));

    // ---- ldmatrix source addresses (relative to tile buf base) --------------
    const int wr = w >> 2, wc = w & 3;
    const int obase = wr * 32, ibase = wc * 64;

    uint32_t a_addr[2];
#pragma unroll
    for (int mt = 0; mt < 2; mt++) {
        int b  = (l & 7) + ((l >> 4) << 3);
        int ch = ((obase + mt * 16) >> 3) + ((l >> 3) & 1);
        a_addr[mt] = (uint32_t)(b * 256 + ((ch ^ (b & 7)) << 4));
    }
    uint32_t b_addr[4];
#pragma unroll
    for (int np = 0; np < 4; np++) {
        int b  = (l & 7) + (((l >> 3) & 1) << 3);
        int ch = ((ibase + np * 16) >> 3) + ((l >> 4) & 1);
        b_addr[np] = (uint32_t)(b * 512 + ((ch ^ (b & 7)) << 4));
    }

    // ---- prologue staging: steps t0..t0+3, one group per step ---------------
#pragma unroll
    for (int p = 0; p < 4; p++) {
        const char* src = (const char*)gin + (size_t)(t0 + p) * IN_SLAB + gi0;
#pragma unroll
        for (int q = 0; q < 4; q++)
            cp16(sb + p * SI_STEP + si0 + q * 8192, src + q * 8192);
        CP_COMMIT();
    }

    // ---- state: bf16x2 trace (zero-init), bf16x2 G accumulator --------------
    uint32_t tr[8];
#pragma unroll
    for (int j = 0; j < 8; j++) tr[j] = 0u;
    uint32_t g4[4];
#pragma unroll
    for (int j = 0; j < 4; j++) g4[j] = 0u;
    uint32_t wgtv = BF_HALF2;   // 0.5^{s+1} packed

    float acc[2][8][4];
#pragma unroll
    for (int mt = 0; mt < 2; mt++)
#pragma unroll
        for (int nt = 0; nt < 8; nt++)
#pragma unroll
            for (int r = 0; r < 4; r++) acc[mt][nt][r] = 0.0f;

    // out values for the step about to be produced
    float4 voA[2];
    {
        const float4* po = reinterpret_cast<const float4*>(gout)
                         + (size_t)t0 * OUT_SLAB + go0;
#pragma unroll
        for (int q = 0; q < 2; q++) voA[q] = po[q * 512];
    }

    // produce(sp): bf16 trace update + tiles for step sp, accumulate G,
    // refill staging with sp+4, prefetch out(sp+1). voA holds out(sp).
    auto produce = [&](int sp) {
        const int slot = sp & 3;
        const int buf  = sp & 1;
        CP_WAIT3();   // staging slot for step sp complete (self-filled)
        const char* sg = smem + slot * SI_STEP + si0;
        char* td = smem + TR_OFF + buf * TR_BSZ + stsin0;
#pragma unroll
        for (int q = 0; q < 4; q++) {
            float4 v = *reinterpret_cast<const float4*>(sg + q * 8192);
            uint32_t i01 = cvt2bf(v.y, v.x);
            uint32_t i23 = cvt2bf(v.w, v.z);
            tr[2 * q]     = hfma2(tr[2 * q],     BF_HALF2, i01);
            tr[2 * q + 1] = hfma2(tr[2 * q + 1], BF_HALF2, i23);
            *reinterpret_cast<uint2*>(td + q * 4096) =
                make_uint2(tr[2 * q], tr[2 * q + 1]);
        }
        char* od = smem + OT_OFF + buf * OT_BSZ + stsout0;
#pragma unroll
        for (int q = 0; q < 2; q++) {
            uint32_t o01 = cvt2bf(voA[q].y, voA[q].x);
            uint32_t o23 = cvt2bf(voA[q].w, voA[q].z);
            *reinterpret_cast<uint2*>(od + q * 4096) = make_uint2(o01, o23);
            g4[2 * q]     = hfma2(o01, wgtv, g4[2 * q]);
            g4[2 * q + 1] = hfma2(o23, wgtv, g4[2 * q + 1]);
        }
        wgtv = hfma2(wgtv, BF_HALF2, 0u);   // wgt *= 0.5 (packed)
        // prefetch out(sp+1)
        if (sp + 1 < len) {
            const float4* po = reinterpret_cast<const float4*>(gout)
                             + (size_t)(t0 + sp + 1) * OUT_SLAB + go0;
#pragma unroll
            for (int q = 0; q < 2; q++) voA[q] = po[q * 512];
        }
        // refill this slot with step sp+4
        if (sp + 4 < len) {
            const char* src = (const char*)gin + (size_t)(t0 + sp + 4) * IN_SLAB + gi0;
#pragma unroll
            for (int q = 0; q < 4; q++)
                cp16(sb + slot * SI_STEP + si0 + q * 8192, src + q * 8192);
        }
        CP_COMMIT();
    };

    auto do_mma = [&](int buf) {
        const uint32_t abase = sb + OT_OFF + buf * OT_BSZ;
        const uint32_t bbase = sb + TR_OFF + buf * TR_BSZ;
#pragma unroll
        for (int kb = 0; kb < 2; kb++) {
            uint32_t af[2][4];
            ldsm4t(af[0], abase + a_addr[0] + kb * 16 * 256);
            ldsm4t(af[1], abase + a_addr[1] + kb * 16 * 256);
#pragma unroll
            for (int np = 0; np < 4; np++) {
                uint32_t bf[4];
                ldsm4t(bf, bbase + b_addr[np] + kb * 16 * 512);
#pragma unroll
                for (int mt = 0; mt < 2; mt++) {
                    mma16816(acc[mt][2 * np],     af[mt], bf);
                    mma16816(acc[mt][2 * np + 1], af[mt], bf + 2);
                }
            }
        }
    };

    produce(0);
    __syncthreads();

    for (int s = 0; s < len; s++) {
        if ((w & 1) == 0) {
            do_mma(s & 1);
            if (s + 1 < len) produce(s + 1);
        } else {
            if (s + 1 < len) produce(s + 1);
            do_mma(s & 1);
        }
        __syncthreads();
    }

    // ---- store TE (bf16x2 end-of-chunk trace) and G to scratch --------------
    {
        uint32_t* te = g_TE_u + ((size_t)cx * B_DIM + (b0 + bi)) * (N_IN / 2)
                     + ((tid & 63) << 1);
#pragma unroll
        for (int q = 0; q < 4; q++)
            *reinterpret_cast<uint2*>(te + q * (8 * (N_IN / 2))) =
                make_uint2(tr[2 * q], tr[2 * q + 1]);
        uint32_t* gg = g_G_u + ((size_t)cx * B_DIM + (b0 + bo)) * (N_OUT / 2)
                     + ((tid & 31) << 1);
#pragma unroll
        for (int q = 0; q < 2; q++)
            *reinterpret_cast<uint2*>(gg + q * (16 * (N_OUT / 2))) =
                make_uint2(g4[2 * q], g4[2 * q + 1]);
    }

    // ---- epilogue: vector reductions into dw --------------------------------
#pragma unroll
    for (int mt = 0; mt < 2; mt++) {
#pragma unroll
        for (int nt = 0; nt < 8; nt++) {
            const int o = obase + mt * 16 + (l >> 2);
            const int i = ibase + nt * 8 + ((l & 3) << 1);
            float* p = dw + (size_t)o * N_IN + i;
            asm volatile("red.global.add.v2.f32 [%0], {%1,%2};"
                         :: "l"(p), "f"(acc[mt][nt][0]), "f"(acc[mt][nt][1]) : "memory");
            asm volatile("red.global.add.v2.f32 [%0], {%1,%2};"
                         :: "l"(p + 8 * N_IN), "f"(acc[mt][nt][2]), "f"(acc[mt][nt][3]) : "memory");
        }
    }
}

// ---------------------------------------------------------------------------
// Cross-chunk correction: dw += TE(c-1)^T * G(c), K = 128 (batch), c = 1..GT-1.
__global__ void __launch_bounds__(NTHR, 1)
stdp_corr_kernel(float* __restrict__ dw)
{
    extern __shared__ __align__(1024) char smem[];
    const uint32_t sb = smem_u32(smem);
    const int tid = threadIdx.x;
    const int w   = tid >> 5;
    const int l   = tid & 31;
    const int c   = blockIdx.x + 1;

    // ---- load TE(c-1) / G(c) (bf16x2) -> swizzled tiles ---------------------
    {
        const uint32_t* te = g_TE_u + (size_t)(c - 1) * (B_DIM * N_IN / 2);
#pragma unroll
        for (int q = 0; q < 16; q++) {
            int f  = tid + 512 * q;
            int b  = f >> 6;
            int i4 = (f & 63) << 2;
            uint2 v = *reinterpret_cast<const uint2*>(te + b * (N_IN / 2) + (i4 >> 1));
            uint32_t off = (uint32_t)(b * 512 + (((i4 >> 3) ^ (b & 7)) << 4) + ((i4 & 7) << 1));
            *reinterpret_cast<uint2*>(smem + C_TE_OFF + off) = v;
        }
        const uint32_t* gg = g_G_u + (size_t)c * (B_DIM * N_OUT / 2);
#pragma unroll
        for (int q = 0; q < 8; q++) {
            int f  = tid + 512 * q;
            int b  = f >> 5;
            int o4 = (f & 31) << 2;
            uint2 v = *reinterpret_cast<const uint2*>(gg + b * (N_OUT / 2) + (o4 >> 1));
            uint32_t off = (uint32_t)(b * 256 + (((o4 >> 3) ^ (b & 7)) << 4) + ((o4 & 7) << 1));
            *reinterpret_cast<uint2*>(smem + C_G_OFF + off) = v;
        }
    }
    __syncthreads();

    // ---- MMA: warp tile 32(o) x 64(i), K = 128 ------------------------------
    const int wr = w >> 2, wc = w & 3;
    const int obase = wr * 32, ibase = wc * 64;

    uint32_t a_addr[2];
#pragma unroll
    for (int mt = 0; mt < 2; mt++) {
        int b  = (l & 7) + ((l >> 4) << 3);
        int ch = ((obase + mt * 16) >> 3) + ((l >> 3) & 1);
        a_addr[mt] = (uint32_t)(b * 256 + ((ch ^ (b & 7)) << 4));
    }
    uint32_t b_addr[4];
#pragma unroll
    for (int np = 0; np < 4; np++) {
        int b  = (l & 7) + (((l >> 3) & 1) << 3);
        int ch = ((ibase + np * 16) >> 3) + ((l >> 4) & 1);
        b_addr[np] = (uint32_t)(b * 512 + ((ch ^ (b & 7)) << 4));
    }

    float acc[2][8][4];
#pragma unroll
    for (int mt = 0; mt < 2; mt++)
#pragma unroll
        for (int nt = 0; nt < 8; nt++)
#pragma unroll
            for (int r = 0; r < 4; r++) acc[mt][nt][r] = 0.0f;

#pragma unroll
    for (int kb = 0; kb < 8; kb++) {
        uint32_t af[2][4];
        ldsm4t(af[0], sb + C_G_OFF + a_addr[0] + kb * 16 * 256);
        ldsm4t(af[1], sb + C_G_OFF + a_addr[1] + kb * 16 * 256);
#pragma unroll
        for (int np = 0; np < 4; np++) {
            uint32_t bf[4];
            ldsm4t(bf, sb + C_TE_OFF + b_addr[np] + kb * 16 * 512);
#pragma unroll
            for (int mt = 0; mt < 2; mt++) {
                mma16816(acc[mt][2 * np],     af[mt], bf);
                mma16816(acc[mt][2 * np + 1], af[mt], bf + 2);
            }
        }
    }

#pragma unroll
    for (int mt = 0; mt < 2; mt++) {
#pragma unroll
        for (int nt = 0; nt < 8; nt++) {
            const int o = obase + mt * 16 + (l >> 2);
            const int i = ibase + nt * 8 + ((l & 3) << 1);
            float* p = dw + (size_t)o * N_IN + i;
            asm volatile("red.global.add.v2.f32 [%0], {%1,%2};"
                         :: "l"(p), "f"(acc[mt][nt][0]), "f"(acc[mt][nt][1]) : "memory");
            asm volatile("red.global.add.v2.f32 [%0], {%1,%2};"
                         :: "l"(p + 8 * N_IN), "f"(acc[mt][nt][2]), "f"(acc[mt][nt][3]) : "memory");
        }
    }
}

extern "C" void kernel_launch(void* const* d_in, const int* in_sizes, int n_in,
                              void* d_out, int out_size) {
    (void)in_sizes; (void)n_in; (void)out_size;
    const float* gin  = (const float*)d_in[0];   // in_spikes  [T, B, N_IN]
    const float* gout = (const float*)d_in[1];   // out_spikes [T, B, N_OUT]
    float* dw = (float*)d_out;                   // [N_OUT, N_IN]

    stdp_zero_kernel<<<(N_OUT * N_IN / 4) / NTHR, NTHR>>>((float4*)dw);

    cudaFuncSetAttribute(stdp_main_kernel,
                         cudaFuncAttributeMaxDynamicSharedMemorySize, SM_TOTAL);
    dim3 grid(GT, NBS);
    stdp_main_kernel<<<grid, NTHR, SM_TOTAL>>>(gin, gout, dw);

    cudaFuncSetAttribute(stdp_corr_kernel,
                         cudaFuncAttributeMaxDynamicSharedMemorySize, C_SM_TOT);
    stdp_corr_kernel<<<GT - 1, NTHR, C_SM_TOT>>>(dw);
}

// round 12
// speedup vs baseline: 1.1632x; 1.0309x over previous
#include <cuda_runtime.h>
#include <cuda_bf16.h>
#include <cstdint>

// ---------------------------------------------------------------------------
// STDP delta_w on GB300 — base-sm_103-legal tensor core path (mma.sync bf16).
//
//   trace_t = 0.5*trace_{t-1} + in_t
//   dw[o,i] = sum_{t,b} trace[t,b,i] * out[t,b,o]
//
// R11: trace recursion carried IN the bf16 MMA tile (each thread reads back
// its own slots from the previous tile buffer), deleting the fp32 cp.async
// staging entirely (crossbar 184->136 KB/step) and moving `in` to a
// distance-1 direct-LDG register prefetch. Chunk decomposition retained:
//   dw = sum_c dw_intra(c) + sum_{c>=1} TE(c-1)^T * G(c)
// dw zeroed via cudaMemsetAsync (no zero kernel).
// ---------------------------------------------------------------------------

#define T_STEPS 2048
#define B_DIM   128
#define N_IN    256
#define N_OUT   128
#define GT      37                  // time chunks (len 55 or 56)
#define KB      32
#define NBS     (B_DIM / KB)        // 4
#define NTHR    512

// Static smem, main kernel (48 KB):
//   [0, 32768)       trace bf16 tile: 2 bufs x 16KB (32 rows x 512B, swizzled)
//   [32768, 49152)   out   bf16 tile: 2 bufs x  8KB (32 rows x 256B, swizzled)
#define TR_OFF   0
#define TR_BSZ   16384
#define OT_OFF   32768
#define OT_BSZ   8192
#define SM_TOTAL 49152

// Correction kernel smem: TE tile 128x512B = 64KB, G tile 128x256B = 32KB
#define C_TE_OFF 0
#define C_G_OFF  65536
#define C_SM_TOT 98304

#define IN_SLAB  (B_DIM * N_IN  * 4)   // bytes per timestep of gin
#define OUT_SLAB (B_DIM * N_OUT / 4)   // float4 per timestep of gout

#define BF_HALF2 0x3F003F00u           // bf16x2 (0.5, 0.5)

// cross-chunk scratch, bf16x2 packed
__device__ uint32_t g_TE_u[GT * B_DIM * (N_IN / 2)];    // [chunk][b][i/2]
__device__ uint32_t g_G_u [GT * B_DIM * (N_OUT / 2)];   // [chunk][b][o/2]

__device__ __forceinline__ uint32_t smem_u32(const void* p) {
    uint32_t a;
    asm("{ .reg .u64 t; cvta.to.shared.u64 t, %1; cvt.u32.u64 %0, t; }" : "=r"(a) : "l"(p));
    return a;
}

__device__ __forceinline__ void ldsm4t(uint32_t* d, uint32_t a) {
    asm volatile("ldmatrix.sync.aligned.m8n8.x4.trans.shared.b16 {%0,%1,%2,%3}, [%4];"
                 : "=r"(d[0]), "=r"(d[1]), "=r"(d[2]), "=r"(d[3]) : "r"(a));
}

__device__ __forceinline__ void mma16816(float* d, const uint32_t* a, const uint32_t* b) {
    asm volatile(
        "mma.sync.aligned.m16n8k16.row.col.f32.bf16.bf16.f32 "
        "{%0,%1,%2,%3},{%4,%5,%6,%7},{%8,%9},{%0,%1,%2,%3};"
        : "+f"(d[0]), "+f"(d[1]), "+f"(d[2]), "+f"(d[3])
        : "r"(a[0]), "r"(a[1]), "r"(a[2]), "r"(a[3]), "r"(b[0]), "r"(b[1]));
}

// d = a*b + c in packed bf16x2
__device__ __forceinline__ uint32_t hfma2(uint32_t a, uint32_t b, uint32_t c) {
    uint32_t d;
    asm("fma.rn.bf16x2 %0, %1, %2, %3;" : "=r"(d) : "r"(a), "r"(b), "r"(c));
    return d;
}

// pack (lo, hi) floats -> bf16x2
__device__ __forceinline__ uint32_t cvt2bf(float hi, float lo) {
    uint32_t r;
    asm("cvt.rn.bf16x2.f32 %0, %1, %2;" : "=r"(r) : "f"(hi), "f"(lo));
    return r;
}

// ---------------------------------------------------------------------------
__global__ void __launch_bounds__(NTHR, 1)
stdp_main_kernel(const float* __restrict__ gin,   // [T, B, N_IN]
                 const float* __restrict__ gout,  // [T, B, N_OUT]
                 float* __restrict__ dw)          // [N_OUT, N_IN]
{
    __shared__ __align__(1024) char smem[SM_TOTAL];
    const uint32_t sb = smem_u32(smem);
    const int tid = threadIdx.x;
    const int w   = tid >> 5;
    const int l   = tid & 31;

    const int cx  = blockIdx.x;
    const int t0  = (cx * T_STEPS) / GT;
    const int t1  = ((cx + 1) * T_STEPS) / GT;
    const int len = t1 - t0;                 // 55 or 56
    const int b0  = blockIdx.y * KB;

    // ---- affine per-thread base offsets -------------------------------------
    const int bi  = tid >> 6;               // in-base batch row (0..7)
    const int i4  = (tid & 63) << 2;
    const int gi0 = ((b0 + bi) * (N_IN / 4) + (tid & 63)) * 16;      // bytes
    const uint32_t stsin0 = (uint32_t)(bi * 512 + (((i4 >> 3) ^ (bi & 7)) << 4)
                                       + ((i4 & 7) << 1));
    const int bo  = tid >> 5;               // out-base batch row (0..15)
    const int o4  = (tid & 31) << 2;
    const int go0 = (b0 + bo) * (N_OUT / 4) + (tid & 31);             // float4
    const uint32_t stsout0 = (uint32_t)(bo * 256 + (((o4 >> 3) ^ (bo & 7)) << 4)
                                        + ((o4 & 7) << 1));

    // ---- ldmatrix source addresses (relative to tile buf base) --------------
    const int wr = w >> 2, wc = w & 3;
    const int obase = wr * 32, ibase = wc * 64;

    uint32_t a_addr[2];
#pragma unroll
    for (int mt = 0; mt < 2; mt++) {
        int b  = (l & 7) + ((l >> 4) << 3);
        int ch = ((obase + mt * 16) >> 3) + ((l >> 3) & 1);
        a_addr[mt] = (uint32_t)(b * 256 + ((ch ^ (b & 7)) << 4));
    }
    uint32_t b_addr[4];
#pragma unroll
    for (int np = 0; np < 4; np++) {
        int b  = (l & 7) + (((l >> 3) & 1) << 3);
        int ch = ((ibase + np * 16) >> 3) + ((l >> 4) & 1);
        b_addr[np] = (uint32_t)(b * 512 + ((ch ^ (b & 7)) << 4));
    }

    // ---- zero the "previous" trace buffer (buf 1); each thread its own slots
    {
        char* tz = smem + TR_OFF + TR_BSZ + stsin0;
#pragma unroll
        for (int q = 0; q < 4; q++)
            *reinterpret_cast<uint2*>(tz + q * 4096) = make_uint2(0u, 0u);
    }

    // ---- state --------------------------------------------------------------
    uint32_t g4[4];
#pragma unroll
    for (int j = 0; j < 4; j++) g4[j] = 0u;
    uint32_t wgtv = BF_HALF2;   // 0.5^{s+1} packed

    float acc[2][8][4];
#pragma unroll
    for (int mt = 0; mt < 2; mt++)
#pragma unroll
        for (int nt = 0; nt < 8; nt++)
#pragma unroll
            for (int r = 0; r < 4; r++) acc[mt][nt][r] = 0.0f;

    // distance-1 register prefetch of in (4 x float4) and out (2 x float4)
    float4 vin[4], voA[2];
    {
        const char* src = (const char*)gin + (size_t)t0 * IN_SLAB + gi0;
#pragma unroll
        for (int q = 0; q < 4; q++)
            vin[q] = *reinterpret_cast<const float4*>(src + q * 8192);
        const float4* po = reinterpret_cast<const float4*>(gout)
                         + (size_t)t0 * OUT_SLAB + go0;
#pragma unroll
        for (int q = 0; q < 2; q++) voA[q] = po[q * 512];
    }

    // produce(sp): tile(sp) = 0.5*tile(sp-1) + in(sp) (bf16, in-tile recursion),
    // out tile + G accumulation, then prefetch step sp+1 into vin/voA.
    auto produce = [&](int sp) {
        const int buf = sp & 1;
        char* td = smem + TR_OFF + buf * TR_BSZ + stsin0;
        const char* tp = smem + TR_OFF + (1 - buf) * TR_BSZ + stsin0;
#pragma unroll
        for (int q = 0; q < 4; q++) {
            uint2 prev = *reinterpret_cast<const uint2*>(tp + q * 4096);
            uint32_t i01 = cvt2bf(vin[q].y, vin[q].x);
            uint32_t i23 = cvt2bf(vin[q].w, vin[q].z);
            uint2 cur;
            cur.x = hfma2(prev.x, BF_HALF2, i01);
            cur.y = hfma2(prev.y, BF_HALF2, i23);
            *reinterpret_cast<uint2*>(td + q * 4096) = cur;
        }
        char* od = smem + OT_OFF + buf * OT_BSZ + stsout0;
#pragma unroll
        for (int q = 0; q < 2; q++) {
            uint32_t o01 = cvt2bf(voA[q].y, voA[q].x);
            uint32_t o23 = cvt2bf(voA[q].w, voA[q].z);
            *reinterpret_cast<uint2*>(od + q * 4096) = make_uint2(o01, o23);
            g4[2 * q]     = hfma2(o01, wgtv, g4[2 * q]);
            g4[2 * q + 1] = hfma2(o23, wgtv, g4[2 * q + 1]);
        }
        wgtv = hfma2(wgtv, BF_HALF2, 0u);   // wgt *= 0.5 (packed)
        // prefetch step sp+1 (consumed by produce(sp+1) next iteration)
        if (sp + 1 < len) {
            const char* src = (const char*)gin + (size_t)(t0 + sp + 1) * IN_SLAB + gi0;
#pragma unroll
            for (int q = 0; q < 4; q++)
                vin[q] = *reinterpret_cast<const float4*>(src + q * 8192);
            const float4* po = reinterpret_cast<const float4*>(gout)
                             + (size_t)(t0 + sp + 1) * OUT_SLAB + go0;
#pragma unroll
            for (int q = 0; q < 2; q++) voA[q] = po[q * 512];
        }
    };

    auto do_mma = [&](int buf) {
        const uint32_t abase = sb + OT_OFF + buf * OT_BSZ;
        const uint32_t bbase = sb + TR_OFF + buf * TR_BSZ;
#pragma unroll
        for (int kb = 0; kb < 2; kb++) {
            uint32_t af[2][4];
            ldsm4t(af[0], abase + a_addr[0] + kb * 16 * 256);
            ldsm4t(af[1], abase + a_addr[1] + kb * 16 * 256);
#pragma unroll
            for (int np = 0; np < 4; np++) {
                uint32_t bf[4];
                ldsm4t(bf, bbase + b_addr[np] + kb * 16 * 512);
#pragma unroll
                for (int mt = 0; mt < 2; mt++) {
                    mma16816(acc[mt][2 * np],     af[mt], bf);
                    mma16816(acc[mt][2 * np + 1], af[mt], bf + 2);
                }
            }
        }
    };

    produce(0);
    __syncthreads();

    for (int s = 0; s < len; s++) {
        if ((w & 1) == 0) {
            do_mma(s & 1);
            if (s + 1 < len) produce(s + 1);
        } else {
            if (s + 1 < len) produce(s + 1);
            do_mma(s & 1);
        }
        __syncthreads();
    }

    // ---- store TE (final trace tile, own slots) and G to scratch ------------
    {
        const char* tf = smem + TR_OFF + ((len - 1) & 1) * TR_BSZ + stsin0;
        uint32_t* te = g_TE_u + ((size_t)cx * B_DIM + (b0 + bi)) * (N_IN / 2)
                     + ((tid & 63) << 1);
#pragma unroll
        for (int q = 0; q < 4; q++) {
            uint2 v = *reinterpret_cast<const uint2*>(tf + q * 4096);
            *reinterpret_cast<uint2*>(te + q * (8 * (N_IN / 2))) = v;
        }
        uint32_t* gg = g_G_u + ((size_t)cx * B_DIM + (b0 + bo)) * (N_OUT / 2)
                     + ((tid & 31) << 1);
#pragma unroll
        for (int q = 0; q < 2; q++)
            *reinterpret_cast<uint2*>(gg + q * (16 * (N_OUT / 2))) =
                make_uint2(g4[2 * q], g4[2 * q + 1]);
    }

    // ---- epilogue: vector reductions into dw --------------------------------
#pragma unroll
    for (int mt = 0; mt < 2; mt++) {
#pragma unroll
        for (int nt = 0; nt < 8; nt++) {
            const int o = obase + mt * 16 + (l >> 2);
            const int i = ibase + nt * 8 + ((l & 3) << 1);
            float* p = dw + (size_t)o * N_IN + i;
            asm volatile("red.global.add.v2.f32 [%0], {%1,%2};"
                         :: "l"(p), "f"(acc[mt][nt][0]), "f"(acc[mt][nt][1]) : "memory");
            asm volatile("red.global.add.v2.f32 [%0], {%1,%2};"
                         :: "l"(p + 8 * N_IN), "f"(acc[mt][nt][2]), "f"(acc[mt][nt][3]) : "memory");
        }
    }
}

// ---------------------------------------------------------------------------
// Cross-chunk correction: dw += TE(c-1)^T * G(c), K = 128 (batch), c = 1..GT-1.
__global__ void __launch_bounds__(NTHR, 1)
stdp_corr_kernel(float* __restrict__ dw)
{
    extern __shared__ __align__(1024) char smem[];
    const uint32_t sb = smem_u32(smem);
    const int tid = threadIdx.x;
    const int w   = tid >> 5;
    const int l   = tid & 31;
    const int c   = blockIdx.x + 1;

    // ---- load TE(c-1) / G(c) (bf16x2) -> swizzled tiles ---------------------
    {
        const uint32_t* te = g_TE_u + (size_t)(c - 1) * (B_DIM * N_IN / 2);
#pragma unroll
        for (int q = 0; q < 16; q++) {
            int f  = tid + 512 * q;
            int b  = f >> 6;
            int i4 = (f & 63) << 2;
            uint2 v = *reinterpret_cast<const uint2*>(te + b * (N_IN / 2) + (i4 >> 1));
            uint32_t off = (uint32_t)(b * 512 + (((i4 >> 3) ^ (b & 7)) << 4) + ((i4 & 7) << 1));
            *reinterpret_cast<uint2*>(smem + C_TE_OFF + off) = v;
        }
        const uint32_t* gg = g_G_u + (size_t)c * (B_DIM * N_OUT / 2);
#pragma unroll
        for (int q = 0; q < 8; q++) {
            int f  = tid + 512 * q;
            int b  = f >> 5;
            int o4 = (f & 31) << 2;
            uint2 v = *reinterpret_cast<const uint2*>(gg + b * (N_OUT / 2) + (o4 >> 1));
            uint32_t off = (uint32_t)(b * 256 + (((o4 >> 3) ^ (b & 7)) << 4) + ((o4 & 7) << 1));
            *reinterpret_cast<uint2*>(smem + C_G_OFF + off) = v;
        }
    }
    __syncthreads();

    // ---- MMA: warp tile 32(o) x 64(i), K = 128 ------------------------------
    const int wr = w >> 2, wc = w & 3;
    const int obase = wr * 32, ibase = wc * 64;

    uint32_t a_addr[2];
#pragma unroll
    for (int mt = 0; mt < 2; mt++) {
        int b  = (l & 7) + ((l >> 4) << 3);
        int ch = ((obase + mt * 16) >> 3) + ((l >> 3) & 1);
        a_addr[mt] = (uint32_t)(b * 256 + ((ch ^ (b & 7)) << 4));
    }
    uint32_t b_addr[4];
#pragma unroll
    for (int np = 0; np < 4; np++) {
        int b  = (l & 7) + (((l >> 3) & 1) << 3);
        int ch = ((ibase + np * 16) >> 3) + ((l >> 4) & 1);
        b_addr[np] = (uint32_t)(b * 512 + ((ch ^ (b & 7)) << 4));
    }

    float acc[2][8][4];
#pragma unroll
    for (int mt = 0; mt < 2; mt++)
#pragma unroll
        for (int nt = 0; nt < 8; nt++)
#pragma unroll
            for (int r = 0; r < 4; r++) acc[mt][nt][r] = 0.0f;

#pragma unroll
    for (int kb = 0; kb < 8; kb++) {
        uint32_t af[2][4];
        ldsm4t(af[0], sb + C_G_OFF + a_addr[0] + kb * 16 * 256);
        ldsm4t(af[1], sb + C_G_OFF + a_addr[1] + kb * 16 * 256);
#pragma unroll
        for (int np = 0; np < 4; np++) {
            uint32_t bf[4];
            ldsm4t(bf, sb + C_TE_OFF + b_addr[np] + kb * 16 * 512);
#pragma unroll
            for (int mt = 0; mt < 2; mt++) {
                mma16816(acc[mt][2 * np],     af[mt], bf);
                mma16816(acc[mt][2 * np + 1], af[mt], bf + 2);
            }
        }
    }

#pragma unroll
    for (int mt = 0; mt < 2; mt++) {
#pragma unroll
        for (int nt = 0; nt < 8; nt++) {
            const int o = obase + mt * 16 + (l >> 2);
            const int i = ibase + nt * 8 + ((l & 3) << 1);
            float* p = dw + (size_t)o * N_IN + i;
            asm volatile("red.global.add.v2.f32 [%0], {%1,%2};"
                         :: "l"(p), "f"(acc[mt][nt][0]), "f"(acc[mt][nt][1]) : "memory");
            asm volatile("red.global.add.v2.f32 [%0], {%1,%2};"
                         :: "l"(p + 8 * N_IN), "f"(acc[mt][nt][2]), "f"(acc[mt][nt][3]) : "memory");
        }
    }
}

extern "C" void kernel_launch(void* const* d_in, const int* in_sizes, int n_in,
                              void* d_out, int out_size) {
    (void)in_sizes; (void)n_in;
    const float* gin  = (const float*)d_in[0];   // in_spikes  [T, B, N_IN]
    const float* gout = (const float*)d_in[1];   // out_spikes [T, B, N_OUT]
    float* dw = (float*)d_out;                   // [N_OUT, N_IN]

    cudaMemsetAsync(dw, 0, (size_t)out_size * sizeof(float), 0);

    dim3 grid(GT, NBS);
    stdp_main_kernel<<<grid, NTHR>>>(gin, gout, dw);

    cudaFuncSetAttribute(stdp_corr_kernel,
                         cudaFuncAttributeMaxDynamicSharedMemorySize, C_SM_TOT);
    stdp_corr_kernel<<<GT - 1, NTHR, C_SM_TOT>>>(dw);
}

// round 13
// speedup vs baseline: 1.1834x; 1.0174x over previous
#include <cuda_runtime.h>
#include <cuda_bf16.h>
#include <cstdint>

// ---------------------------------------------------------------------------
// STDP delta_w on GB300 — base-sm_103-legal tensor core path (mma.sync bf16).
//
//   trace_t = 0.5*trace_{t-1} + in_t
//   dw[o,i] = sum_{t,b} trace[t,b,i] * out[t,b,o]
//
// R12: (1) correction kernel split 4-way over the K=128 batch dim
//      (grid 36x4, red.global.add accumulates) — was 11.9us on 36 CTAs;
//      (2) trace recursion back in bf16x2 registers (write-only tiles,
//      no read-back LDS, no staging — direct-LDG distance-1 prefetch).
//   dw = sum_c dw_intra(c) + sum_{c>=1} TE(c-1)^T * G(c)
// ---------------------------------------------------------------------------

#define T_STEPS 2048
#define B_DIM   128
#define N_IN    256
#define N_OUT   128
#define GT      37                  // time chunks (len 55 or 56)
#define KB      32
#define NBS     (B_DIM / KB)        // 4
#define NTHR    512

// Static smem, main kernel (48 KB):
//   [0, 32768)       trace bf16 tile: 2 bufs x 16KB (32 rows x 512B, swizzled)
//   [32768, 49152)   out   bf16 tile: 2 bufs x  8KB (32 rows x 256B, swizzled)
#define TR_OFF   0
#define TR_BSZ   16384
#define OT_OFF   32768
#define OT_BSZ   8192
#define SM_TOTAL 49152

// Corr kernel static smem (24 KB): TR slice 32x512B, OT slice 32x256B
#define CR_TR    0
#define CR_OT    16384
#define CR_TOT   24576

#define IN_SLAB  (B_DIM * N_IN  * 4)   // bytes per timestep of gin
#define OUT_SLAB (B_DIM * N_OUT / 4)   // float4 per timestep of gout

#define BF_HALF2 0x3F003F00u           // bf16x2 (0.5, 0.5)

// cross-chunk scratch, bf16x2 packed
__device__ uint32_t g_TE_u[GT * B_DIM * (N_IN / 2)];    // [chunk][b][i/2]
__device__ uint32_t g_G_u [GT * B_DIM * (N_OUT / 2)];   // [chunk][b][o/2]

__device__ __forceinline__ uint32_t smem_u32(const void* p) {
    uint32_t a;
    asm("{ .reg .u64 t; cvta.to.shared.u64 t, %1; cvt.u32.u64 %0, t; }" : "=r"(a) : "l"(p));
    return a;
}

__device__ __forceinline__ void ldsm4t(uint32_t* d, uint32_t a) {
    asm volatile("ldmatrix.sync.aligned.m8n8.x4.trans.shared.b16 {%0,%1,%2,%3}, [%4];"
                 : "=r"(d[0]), "=r"(d[1]), "=r"(d[2]), "=r"(d[3]) : "r"(a));
}

__device__ __forceinline__ void mma16816(float* d, const uint32_t* a, const uint32_t* b) {
    asm volatile(
        "mma.sync.aligned.m16n8k16.row.col.f32.bf16.bf16.f32 "
        "{%0,%1,%2,%3},{%4,%5,%6,%7},{%8,%9},{%0,%1,%2,%3};"
        : "+f"(d[0]), "+f"(d[1]), "+f"(d[2]), "+f"(d[3])
        : "r"(a[0]), "r"(a[1]), "r"(a[2]), "r"(a[3]), "r"(b[0]), "r"(b[1]));
}

__device__ __forceinline__ uint32_t hfma2(uint32_t a, uint32_t b, uint32_t c) {
    uint32_t d;
    asm("fma.rn.bf16x2 %0, %1, %2, %3;" : "=r"(d) : "r"(a), "r"(b), "r"(c));
    return d;
}

__device__ __forceinline__ uint32_t cvt2bf(float hi, float lo) {
    uint32_t r;
    asm("cvt.rn.bf16x2.f32 %0, %1, %2;" : "=r"(r) : "f"(hi), "f"(lo));
    return r;
}

// ---------------------------------------------------------------------------
__global__ void __launch_bounds__(NTHR, 1)
stdp_main_kernel(const float* __restrict__ gin,   // [T, B, N_IN]
                 const float* __restrict__ gout,  // [T, B, N_OUT]
                 float* __restrict__ dw)          // [N_OUT, N_IN]
{
    __shared__ __align__(1024) char smem[SM_TOTAL];
    const uint32_t sb = smem_u32(smem);
    const int tid = threadIdx.x;
    const int w   = tid >> 5;
    const int l   = tid & 31;

    const int cx  = blockIdx.x;
    const int t0  = (cx * T_STEPS) / GT;
    const int t1  = ((cx + 1) * T_STEPS) / GT;
    const int len = t1 - t0;                 // 55 or 56
    const int b0  = blockIdx.y * KB;

    // ---- affine per-thread base offsets -------------------------------------
    const int bi  = tid >> 6;               // in-base batch row (0..7)
    const int i4  = (tid & 63) << 2;
    const int gi0 = ((b0 + bi) * (N_IN / 4) + (tid & 63)) * 16;      // bytes
    const uint32_t stsin0 = (uint32_t)(bi * 512 + (((i4 >> 3) ^ (bi & 7)) << 4)
                                       + ((i4 & 7) << 1));
    const int bo  = tid >> 5;               // out-base batch row (0..15)
    const int o4  = (tid & 31) << 2;
    const int go0 = (b0 + bo) * (N_OUT / 4) + (tid & 31);             // float4
    const uint32_t stsout0 = (uint32_t)(bo * 256 + (((o4 >> 3) ^ (bo & 7)) << 4)
                                        + ((o4 & 7) << 1));

    // ---- ldmatrix source addresses (relative to tile buf base) --------------
    const int wr = w >> 2, wc = w & 3;
    const int obase = wr * 32, ibase = wc * 64;

    uint32_t a_addr[2];
#pragma unroll
    for (int mt = 0; mt < 2; mt++) {
        int b  = (l & 7) + ((l >> 4) << 3);
        int ch = ((obase + mt * 16) >> 3) + ((l >> 3) & 1);
        a_addr[mt] = (uint32_t)(b * 256 + ((ch ^ (b & 7)) << 4));
    }
    uint32_t b_addr[4];
#pragma unroll
    for (int np = 0; np < 4; np++) {
        int b  = (l & 7) + (((l >> 3) & 1) << 3);
        int ch = ((ibase + np * 16) >> 3) + ((l >> 4) & 1);
        b_addr[np] = (uint32_t)(b * 512 + ((ch ^ (b & 7)) << 4));
    }

    // ---- state: bf16x2 trace in registers, bf16x2 G accumulator -------------
    uint32_t tr[8];
#pragma unroll
    for (int j = 0; j < 8; j++) tr[j] = 0u;
    uint32_t g4[4];
#pragma unroll
    for (int j = 0; j < 4; j++) g4[j] = 0u;
    uint32_t wgtv = BF_HALF2;   // 0.5^{s+1} packed

    float acc[2][8][4];
#pragma unroll
    for (int mt = 0; mt < 2; mt++)
#pragma unroll
        for (int nt = 0; nt < 8; nt++)
#pragma unroll
            for (int r = 0; r < 4; r++) acc[mt][nt][r] = 0.0f;

    // distance-1 register prefetch of in (4 x float4) and out (2 x float4)
    float4 vin[4], voA[2];
    {
        const char* src = (const char*)gin + (size_t)t0 * IN_SLAB + gi0;
#pragma unroll
        for (int q = 0; q < 4; q++)
            vin[q] = *reinterpret_cast<const float4*>(src + q * 8192);
        const float4* po = reinterpret_cast<const float4*>(gout)
                         + (size_t)t0 * OUT_SLAB + go0;
#pragma unroll
        for (int q = 0; q < 2; q++) voA[q] = po[q * 512];
    }

    // produce(sp): trace update in regs, write-only bf16 tiles, G accumulation,
    // then prefetch step sp+1 into vin/voA.
    auto produce = [&](int sp) {
        const int buf = sp & 1;
        char* td = smem + TR_OFF + buf * TR_BSZ + stsin0;
#pragma unroll
        for (int q = 0; q < 4; q++) {
            uint32_t i01 = cvt2bf(vin[q].y, vin[q].x);
            uint32_t i23 = cvt2bf(vin[q].w, vin[q].z);
            tr[2 * q]     = hfma2(tr[2 * q],     BF_HALF2, i01);
            tr[2 * q + 1] = hfma2(tr[2 * q + 1], BF_HALF2, i23);
            *reinterpret_cast<uint2*>(td + q * 4096) =
                make_uint2(tr[2 * q], tr[2 * q + 1]);
        }
        char* od = smem + OT_OFF + buf * OT_BSZ + stsout0;
#pragma unroll
        for (int q = 0; q < 2; q++) {
            uint32_t o01 = cvt2bf(voA[q].y, voA[q].x);
            uint32_t o23 = cvt2bf(voA[q].w, voA[q].z);
            *reinterpret_cast<uint2*>(od + q * 4096) = make_uint2(o01, o23);
            g4[2 * q]     = hfma2(o01, wgtv, g4[2 * q]);
            g4[2 * q + 1] = hfma2(o23, wgtv, g4[2 * q + 1]);
        }
        wgtv = hfma2(wgtv, BF_HALF2, 0u);   // wgt *= 0.5 (packed)
        // prefetch step sp+1
        if (sp + 1 < len) {
            const char* src = (const char*)gin + (size_t)(t0 + sp + 1) * IN_SLAB + gi0;
#pragma unroll
            for (int q = 0; q < 4; q++)
                vin[q] = *reinterpret_cast<const float4*>(src + q * 8192);
            const float4* po = reinterpret_cast<const float4*>(gout)
                             + (size_t)(t0 + sp + 1) * OUT_SLAB + go0;
#pragma unroll
            for (int q = 0; q < 2; q++) voA[q] = po[q * 512];
        }
    };

    auto do_mma = [&](int buf) {
        const uint32_t abase = sb + OT_OFF + buf * OT_BSZ;
        const uint32_t bbase = sb + TR_OFF + buf * TR_BSZ;
#pragma unroll
        for (int kb = 0; kb < 2; kb++) {
            uint32_t af[2][4];
            ldsm4t(af[0], abase + a_addr[0] + kb * 16 * 256);
            ldsm4t(af[1], abase + a_addr[1] + kb * 16 * 256);
#pragma unroll
            for (int np = 0; np < 4; np++) {
                uint32_t bf[4];
                ldsm4t(bf, bbase + b_addr[np] + kb * 16 * 512);
#pragma unroll
                for (int mt = 0; mt < 2; mt++) {
                    mma16816(acc[mt][2 * np],     af[mt], bf);
                    mma16816(acc[mt][2 * np + 1], af[mt], bf + 2);
                }
            }
        }
    };

    produce(0);
    __syncthreads();

    for (int s = 0; s < len; s++) {
        if ((w & 1) == 0) {
            do_mma(s & 1);
            if (s + 1 < len) produce(s + 1);
        } else {
            if (s + 1 < len) produce(s + 1);
            do_mma(s & 1);
        }
        __syncthreads();
    }

    // ---- store TE (final trace regs) and G to scratch -----------------------
    {
        uint32_t* te = g_TE_u + ((size_t)cx * B_DIM + (b0 + bi)) * (N_IN / 2)
                     + ((tid & 63) << 1);
#pragma unroll
        for (int q = 0; q < 4; q++)
            *reinterpret_cast<uint2*>(te + q * (8 * (N_IN / 2))) =
                make_uint2(tr[2 * q], tr[2 * q + 1]);
        uint32_t* gg = g_G_u + ((size_t)cx * B_DIM + (b0 + bo)) * (N_OUT / 2)
                     + ((tid & 31) << 1);
#pragma unroll
        for (int q = 0; q < 2; q++)
            *reinterpret_cast<uint2*>(gg + q * (16 * (N_OUT / 2))) =
                make_uint2(g4[2 * q], g4[2 * q + 1]);
    }

    // ---- epilogue: vector reductions into dw --------------------------------
#pragma unroll
    for (int mt = 0; mt < 2; mt++) {
#pragma unroll
        for (int nt = 0; nt < 8; nt++) {
            const int o = obase + mt * 16 + (l >> 2);
            const int i = ibase + nt * 8 + ((l & 3) << 1);
            float* p = dw + (size_t)o * N_IN + i;
            asm volatile("red.global.add.v2.f32 [%0], {%1,%2};"
                         :: "l"(p), "f"(acc[mt][nt][0]), "f"(acc[mt][nt][1]) : "memory");
            asm volatile("red.global.add.v2.f32 [%0], {%1,%2};"
                         :: "l"(p + 8 * N_IN), "f"(acc[mt][nt][2]), "f"(acc[mt][nt][3]) : "memory");
        }
    }
}

// ---------------------------------------------------------------------------
// Cross-chunk correction, 4-way split over the K=128 batch dimension:
//   dw += TE(c-1)[b0:b0+32, :]^T * G(c)[b0:b0+32, :],  c = 1..GT-1.
// Grid (GT-1, NBS) = 144 CTAs; red.global.add accumulates the 4 partials.
__global__ void __launch_bounds__(NTHR, 1)
stdp_corr_kernel(float* __restrict__ dw)
{
    __shared__ __align__(1024) char smem[CR_TOT];
    const uint32_t sb = smem_u32(smem);
    const int tid = threadIdx.x;
    const int w   = tid >> 5;
    const int l   = tid & 31;
    const int c   = blockIdx.x + 1;
    const int b0  = blockIdx.y * KB;

    // ---- load TE(c-1)/G(c) 32-row slices into main-kernel tile geometry -----
    const int bi = tid >> 6;
    const int i4 = (tid & 63) << 2;
    const uint32_t stsin0 = (uint32_t)(bi * 512 + (((i4 >> 3) ^ (bi & 7)) << 4)
                                       + ((i4 & 7) << 1));
    const int bo = tid >> 5;
    const int o4 = (tid & 31) << 2;
    const uint32_t stsout0 = (uint32_t)(bo * 256 + (((o4 >> 3) ^ (bo & 7)) << 4)
                                        + ((o4 & 7) << 1));
    {
        const uint32_t* te = g_TE_u + ((size_t)(c - 1) * B_DIM + (b0 + bi)) * (N_IN / 2)
                           + ((tid & 63) << 1);
#pragma unroll
        for (int q = 0; q < 4; q++) {
            uint2 v = *reinterpret_cast<const uint2*>(te + q * (8 * (N_IN / 2)));
            *reinterpret_cast<uint2*>(smem + CR_TR + stsin0 + q * 4096) = v;
        }
        const uint32_t* gg = g_G_u + ((size_t)c * B_DIM + (b0 + bo)) * (N_OUT / 2)
                           + ((tid & 31) << 1);
#pragma unroll
        for (int q = 0; q < 2; q++) {
            uint2 v = *reinterpret_cast<const uint2*>(gg + q * (16 * (N_OUT / 2)));
            *reinterpret_cast<uint2*>(smem + CR_OT + stsout0 + q * 4096) = v;
        }
    }
    __syncthreads();

    // ---- MMA: warp tile 32(o) x 64(i), K = 32 (2 kb blocks) -----------------
    const int wr = w >> 2, wc = w & 3;
    const int obase = wr * 32, ibase = wc * 64;

    uint32_t a_addr[2];
#pragma unroll
    for (int mt = 0; mt < 2; mt++) {
        int b  = (l & 7) + ((l >> 4) << 3);
        int ch = ((obase + mt * 16) >> 3) + ((l >> 3) & 1);
        a_addr[mt] = (uint32_t)(b * 256 + ((ch ^ (b & 7)) << 4));
    }
    uint32_t b_addr[4];
#pragma unroll
    for (int np = 0; np < 4; np++) {
        int b  = (l & 7) + (((l >> 3) & 1) << 3);
        int ch = ((ibase + np * 16) >> 3) + ((l >> 4) & 1);
        b_addr[np] = (uint32_t)(b * 512 + ((ch ^ (b & 7)) << 4));
    }

    float acc[2][8][4];
#pragma unroll
    for (int mt = 0; mt < 2; mt++)
#pragma unroll
        for (int nt = 0; nt < 8; nt++)
#pragma unroll
            for (int r = 0; r < 4; r++) acc[mt][nt][r] = 0.0f;

#pragma unroll
    for (int kb = 0; kb < 2; kb++) {
        uint32_t af[2][4];
        ldsm4t(af[0], sb + CR_OT + a_addr[0] + kb * 16 * 256);
        ldsm4t(af[1], sb + CR_OT + a_addr[1] + kb * 16 * 256);
#pragma unroll
        for (int np = 0; np < 4; np++) {
            uint32_t bf[4];
            ldsm4t(bf, sb + CR_TR + b_addr[np] + kb * 16 * 512);
#pragma unroll
            for (int mt = 0; mt < 2; mt++) {
                mma16816(acc[mt][2 * np],     af[mt], bf);
                mma16816(acc[mt][2 * np + 1], af[mt], bf + 2);
            }
        }
    }

#pragma unroll
    for (int mt = 0; mt < 2; mt++) {
#pragma unroll
        for (int nt = 0; nt < 8; nt++) {
            const int o = obase + mt * 16 + (l >> 2);
            const int i = ibase + nt * 8 + ((l & 3) << 1);
            float* p = dw + (size_t)o * N_IN + i;
            asm volatile("red.global.add.v2.f32 [%0], {%1,%2};"
                         :: "l"(p), "f"(acc[mt][nt][0]), "f"(acc[mt][nt][1]) : "memory");
            asm volatile("red.global.add.v2.f32 [%0], {%1,%2};"
                         :: "l"(p + 8 * N_IN), "f"(acc[mt][nt][2]), "f"(acc[mt][nt][3]) : "memory");
        }
    }
}

extern "C" void kernel_launch(void* const* d_in, const int* in_sizes, int n_in,
                              void* d_out, int out_size) {
    (void)in_sizes; (void)n_in;
    const float* gin  = (const float*)d_in[0];   // in_spikes  [T, B, N_IN]
    const float* gout = (const float*)d_in[1];   // out_spikes [T, B, N_OUT]
    float* dw = (float*)d_out;                   // [N_OUT, N_IN]

    cudaMemsetAsync(dw, 0, (size_t)out_size * sizeof(float), 0);

    dim3 grid(GT, NBS);
    stdp_main_kernel<<<grid, NTHR>>>(gin, gout, dw);

    dim3 cgrid(GT - 1, NBS);
    stdp_corr_kernel<<<cgrid, NTHR>>>(dw);
}